// round 17
// baseline (speedup 1.0000x reference)
#include <cuda_runtime.h>
#include <cstdint>

// Reference = patchify ∘ depatchify == identity -> 256 MiB D2D copy.
//
// FINAL — measured optimum, confirmed over 3 independent benches.
//
// Sweep (kernel us / DRAM-active):
//   MLP=8 x256: 75.6/80.5    MLP=4 x256: 74.0/82.5
//   MLP=2 x256: 73.4-74.6/81.4-82.8  <- THIS KERNEL (noise band +-0.6us)
//   MLP=2 x512: 74.1/82.2    MLP=1 x256: 78.5/78.9
//   CE memcpy: regression    .cs hints: neutral
//
// Binder: chip-wide path-independent LTS cap (~6.5 TB/s effective r+w at
// natural clock) — proven by CE parity and .cs neutrality. SM pipes idle
// (issue 5.6%). A CE+SM parallel-branch hybrid cannot help: both engines
// share the LTS fabric. dur - kernel = ~8us fixed graph-replay overhead,
// invariant across all 9 tested configs.
//
// 16,777,216 float4; 2 per thread -> 8,388,608 threads -> 32768 blocks x 256.
// Block b covers float4 [b*512, (b+1)*512); thread t touches t, t+256.

__global__ __launch_bounds__(256) void identity_copy_kernel(
    const float4* __restrict__ src, float4* __restrict__ dst)
{
    size_t base = (size_t)blockIdx.x * 512 + threadIdx.x;

    float4 v0 = src[base];
    float4 v1 = src[base + 256];

    dst[base]       = v0;
    dst[base + 256] = v1;
}

extern "C" void kernel_launch(void* const* d_in, const int* in_sizes, int n_in,
                              void* d_out, int out_size)
{
    const float4* src = (const float4*)d_in[0];
    float4* dst = (float4*)d_out;

    identity_copy_kernel<<<32768, 256>>>(src, dst);
}